// round 4
// baseline (speedup 1.0000x reference)
#include <cuda_runtime.h>
#include <math.h>
#include <stdint.h>

// Problem constants
#define B_SZ   256
#define T_SZ   64
#define IN_SZ  500
#define HID    512
#define G4     2048            // 4*HID
#define RAWN   16532           // 500*32 + 32 + 500
#define NA     500
#define NF     32
#define GRIDN  128             // persistent grid size (<= SM count, 1 block/SM)

// ---------------- device scratch (static, no allocation) ----------------
__device__ float g_xg[(size_t)T_SZ * B_SZ * G4];      // input-transform (reused for both layers)
__device__ float g_hseq[(size_t)T_SZ * B_SZ * HID];   // layer-0 hidden sequence
__device__ float g_hA[B_SZ * HID];
__device__ float g_hB[B_SZ * HID];
__device__ float g_raw[(size_t)B_SZ * RAWN];          // FC output
__device__ unsigned long long g_flags[GRIDN];         // grid barrier flags (monotone, zero-init)

__device__ __forceinline__ float sigmf(float x) { return 1.f / (1.f + expf(-x)); }

__device__ __forceinline__ uint32_t f2tf32(float f) {
    uint32_t r;
    asm("cvt.rna.tf32.f32 %0, %1;" : "=r"(r) : "f"(f));
    return r;
}

__device__ __forceinline__ void mma_tf32(float* c, const uint32_t* a, const uint32_t* b) {
    asm volatile(
        "mma.sync.aligned.m16n8k8.row.col.f32.tf32.tf32.f32 "
        "{%0,%1,%2,%3}, {%4,%5,%6,%7}, {%8,%9}, {%0,%1,%2,%3};\n"
        : "+f"(c[0]), "+f"(c[1]), "+f"(c[2]), "+f"(c[3])
        : "r"(a[0]), "r"(a[1]), "r"(a[2]), "r"(a[3]), "r"(b[0]), "r"(b[1]));
}

// ================= persistent fused LSTM layer =================
// grid = 128 blocks (32 hid-chunks x 4 batch-chunks), 256 threads (8 warps).
// Block owns: weight slice [64 gate-cols x 512] in smem (tf32), and the cell
// state c for its 64(batch) x 16(hidden) cells in registers (4 per thread).
// Per step: GEMM  h_in[64x512] @ Wslice^T -> gates[64x64], fused cell update,
// then a distributed-flag grid barrier.
//
// smem word layout (uint32):
//   Wsm : [64][516]   offset 0          (33024 words)
//   Asm0: [64][68]    offset 33024      (4352)
//   Asm1: [64][68]    offset 37376      (4352)
//   Cs  : [64][68] f32 offset 41728     (4352)
#define W_STR 516
#define A_STR 68
#define SM_WORDS (33024 + 4352 + 4352 + 4352)   // 46080 words = 184320 B

__global__ __launch_bounds__(256, 1) void lstm_persist(
    const float* __restrict__ w_hh, int layer)
{
    extern __shared__ uint32_t smraw[];
    uint32_t* Wsm  = smraw;
    uint32_t* Asm0 = smraw + 33024;
    uint32_t* Asm1 = smraw + 37376;
    float*    Cs   = (float*)(smraw + 41728);

    const int tid  = threadIdx.x;
    const int lane = tid & 31;
    const int warp = tid >> 5;
    const int wm   = (warp >> 1) * 16;    // 4 warps along M
    const int wn   = (warp & 1) * 32;     // 2 warps along N
    const int gid  = lane >> 2;
    const int tig  = lane & 3;
    const int nchunk = blockIdx.x & 31;
    const int bchunk = blockIdx.x >> 5;
    const int h0 = nchunk * 16;
    const int m0 = bchunk * 64;

    // ---- load weight slice to smem once (gate-interleaved cols) ----
    // smem row n (0..63) -> w_hh row (n&3)*HID + h0 + (n>>2)
#pragma unroll
    for (int i = 0; i < 32; i++) {
        int s   = tid + (i << 8);          // 0..8191 float4 units
        int row = s >> 7;                  // 0..63
        int kq  = s & 127;                 // float4 index within 512
        int wr  = ((row & 3) << 9) + h0 + (row >> 2);
        float4 v = *(const float4*)&w_hh[(size_t)wr * HID + (kq << 2)];
        uint4 u = { f2tf32(v.x), f2tf32(v.y), f2tf32(v.z), f2tf32(v.w) };
        *(uint4*)&Wsm[row * W_STR + (kq << 2)] = u;
    }

    // barrier base: this block's own flag (only this block writes it)
    const unsigned long long barBase = *(volatile unsigned long long*)&g_flags[blockIdx.x];

    // cell state in registers: thread owns cells (bl = tid>>4 + i*16, j = tid&15)
    float creg[4] = {0.f, 0.f, 0.f, 0.f};
    const int jj  = tid & 15;
    const int bl0 = tid >> 4;

    __syncthreads();

    for (int t = 0; t < T_SZ; t++) {
        const float* h_in = (t & 1) ? g_hB : g_hA;
        float* h_out      = (t & 1) ? g_hA : g_hB;

        if (t > 0) {
            float c[4][4];
#pragma unroll
            for (int nt = 0; nt < 4; nt++)
#pragma unroll
                for (int q = 0; q < 4; q++) c[nt][q] = 0.f;

            // ---- K tile 0 ----
#pragma unroll
            for (int i = 0; i < 4; i++) {
                int s = tid + (i << 8);
                int row = s >> 4, kq = s & 15;
                float4 v = __ldcg((const float4*)&h_in[(size_t)(m0 + row) * HID + (kq << 2)]);
                uint4 u = { f2tf32(v.x), f2tf32(v.y), f2tf32(v.z), f2tf32(v.w) };
                *(uint4*)&Asm0[row * A_STR + (kq << 2)] = u;
            }
            __syncthreads();

            float4 pf[4];
#pragma unroll 1
            for (int kt = 0; kt < 8; kt++) {
                uint32_t* Ab = (kt & 1) ? Asm1 : Asm0;
                const bool pfl = (kt < 7);
                if (pfl) {
#pragma unroll
                    for (int i = 0; i < 4; i++) {
                        int s = tid + (i << 8);
                        int row = s >> 4, kq = s & 15;
                        pf[i] = __ldcg((const float4*)&h_in[
                            (size_t)(m0 + row) * HID + ((kt + 1) << 6) + (kq << 2)]);
                    }
                }
#pragma unroll
                for (int k8 = 0; k8 < 8; k8++) {
                    const int kc = k8 * 8 + tig;
                    uint32_t af[4];
                    af[0] = Ab[(wm + gid)     * A_STR + kc];
                    af[1] = Ab[(wm + gid + 8) * A_STR + kc];
                    af[2] = Ab[(wm + gid)     * A_STR + kc + 4];
                    af[3] = Ab[(wm + gid + 8) * A_STR + kc + 4];
                    const int kw = (kt << 6) + kc;
#pragma unroll
                    for (int nt = 0; nt < 4; nt++) {
                        int cn = wn + nt * 8 + gid;
                        uint32_t bf[2];
                        bf[0] = Wsm[cn * W_STR + kw];
                        bf[1] = Wsm[cn * W_STR + kw + 4];
                        mma_tf32(c[nt], af, bf);
                    }
                }
                if (pfl) {
                    uint32_t* An = (kt & 1) ? Asm0 : Asm1;
#pragma unroll
                    for (int i = 0; i < 4; i++) {
                        int s = tid + (i << 8);
                        int row = s >> 4, kq = s & 15;
                        uint4 u = { f2tf32(pf[i].x), f2tf32(pf[i].y),
                                    f2tf32(pf[i].z), f2tf32(pf[i].w) };
                        *(uint4*)&An[row * A_STR + (kq << 2)] = u;
                    }
                }
                __syncthreads();
            }

            // ---- stage gates to smem ----
#pragma unroll
            for (int nt = 0; nt < 4; nt++) {
                int r  = wm + gid;
                int cb = wn + nt * 8 + 2 * tig;
                Cs[r * A_STR + cb]           = c[nt][0];
                Cs[r * A_STR + cb + 1]       = c[nt][1];
                Cs[(r + 8) * A_STR + cb]     = c[nt][2];
                Cs[(r + 8) * A_STR + cb + 1] = c[nt][3];
            }
            __syncthreads();
        }

        // ---- fused cell update (register-resident c) ----
        const float* xgt = g_xg + (size_t)t * B_SZ * G4;
        const int h = h0 + jj;
#pragma unroll
        for (int i = 0; i < 4; i++) {
            int bl = bl0 + i * 16;
            int b  = m0 + bl;
            const float* xgb = xgt + (size_t)b * G4;
            float gi, gf, gg, go;
            if (t > 0) {
                float4 gv = *(float4*)&Cs[bl * A_STR + jj * 4];
                gi = gv.x; gf = gv.y; gg = gv.z; go = gv.w;
            } else {
                gi = gf = gg = go = 0.f;
            }
            gi += xgb[h];
            gf += xgb[HID + h];
            gg += xgb[2 * HID + h];
            go += xgb[3 * HID + h];
            float cn = sigmf(gf) * creg[i] + sigmf(gi) * tanhf(gg);
            float hn = sigmf(go) * tanhf(cn);
            creg[i] = cn;
            h_out[b * HID + h] = hn;
            if (layer == 0) g_hseq[(size_t)t * B_SZ * HID + b * HID + h] = hn;
        }

        // ---- grid barrier (distributed flags, monotone across replays) ----
        if (t < T_SZ - 1) {
            __threadfence();
            __syncthreads();
            const unsigned long long tgt = barBase + (unsigned long long)(t + 1);
            if (tid == 0)
                *(volatile unsigned long long*)&g_flags[blockIdx.x] = tgt;
            if (tid < GRIDN) {
                while (*(volatile unsigned long long*)&g_flags[tid] < tgt)
                    __nanosleep(64);
            }
            __syncthreads();
        }
    }
}

// ---------------- tensor-core GEMM: C = A @ W^T + bias1 (+bias2) ----------------
union SmemT {
    struct { uint32_t A[2][64][36]; uint32_t B[2][64][36]; } ld;
    float Cs[64][72];
};

__global__ __launch_bounds__(128) void gemm_tc(
    const float* __restrict__ Aext, int asel,
    const float* __restrict__ W,
    const float* __restrict__ bias1, const float* __restrict__ bias2,
    int csel, int N, int K, int remap)
{
    __shared__ SmemT sm;

    const float* A = (asel == 0) ? Aext : (asel == 1 ? g_hseq : g_hA);
    float* C = csel ? g_raw : g_xg;

    const int tid  = threadIdx.x;
    const int lane = tid & 31;
    const int warp = tid >> 5;
    const int wm   = (warp >> 1) * 32;
    const int wn   = (warp & 1) * 32;
    const int gid  = lane >> 2;
    const int tig  = lane & 3;
    const int m0   = blockIdx.y * 64;
    const int n0   = blockIdx.x * 64;

    float c[2][4][4];
#pragma unroll
    for (int mt = 0; mt < 2; mt++)
#pragma unroll
        for (int nt = 0; nt < 4; nt++)
#pragma unroll
            for (int q = 0; q < 4; q++) c[mt][nt][q] = 0.f;

    const int ktiles = (K + 31) >> 5;

#pragma unroll
    for (int i = 0; i < 4; i++) {
        int s = tid + i * 128;
        int row = s >> 3, kq = s & 7;
        int kk = kq * 4;
        float4 va = make_float4(0, 0, 0, 0), vb = make_float4(0, 0, 0, 0);
        if (kk < K) {
            va = *(const float4*)&A[(size_t)(m0 + row) * K + kk];
            int wr = n0 + row;
            if (wr < N) vb = *(const float4*)&W[(size_t)wr * K + kk];
        }
        uint4 ua = {f2tf32(va.x), f2tf32(va.y), f2tf32(va.z), f2tf32(va.w)};
        uint4 ub = {f2tf32(vb.x), f2tf32(vb.y), f2tf32(vb.z), f2tf32(vb.w)};
        *(uint4*)&sm.ld.A[0][row][kq * 4] = ua;
        *(uint4*)&sm.ld.B[0][row][kq * 4] = ub;
    }
    __syncthreads();

    float4 pa[4], pb[4];
    for (int kt = 0; kt < ktiles; kt++) {
        const int buf = kt & 1;
        const bool pf = (kt + 1 < ktiles);
        const int k0n = (kt + 1) << 5;
        if (pf) {
#pragma unroll
            for (int i = 0; i < 4; i++) {
                int s = tid + i * 128;
                int row = s >> 3, kq = s & 7;
                int kk = k0n + kq * 4;
                pa[i] = make_float4(0, 0, 0, 0);
                pb[i] = make_float4(0, 0, 0, 0);
                if (kk < K) {
                    pa[i] = *(const float4*)&A[(size_t)(m0 + row) * K + kk];
                    int wr = n0 + row;
                    if (wr < N) pb[i] = *(const float4*)&W[(size_t)wr * K + kk];
                }
            }
        }
#pragma unroll
        for (int kk8 = 0; kk8 < 4; kk8++) {
            uint32_t af[2][4];
#pragma unroll
            for (int mt = 0; mt < 2; mt++) {
                int r = wm + mt * 16 + gid;
                af[mt][0] = sm.ld.A[buf][r][kk8 * 8 + tig];
                af[mt][1] = sm.ld.A[buf][r + 8][kk8 * 8 + tig];
                af[mt][2] = sm.ld.A[buf][r][kk8 * 8 + tig + 4];
                af[mt][3] = sm.ld.A[buf][r + 8][kk8 * 8 + tig + 4];
            }
#pragma unroll
            for (int nt = 0; nt < 4; nt++) {
                uint32_t bf[2];
                int cn = wn + nt * 8 + gid;
                bf[0] = sm.ld.B[buf][cn][kk8 * 8 + tig];
                bf[1] = sm.ld.B[buf][cn][kk8 * 8 + tig + 4];
                mma_tf32(c[0][nt], af[0], bf);
                mma_tf32(c[1][nt], af[1], bf);
            }
        }
        if (pf) {
#pragma unroll
            for (int i = 0; i < 4; i++) {
                int s = tid + i * 128;
                int row = s >> 3, kq = s & 7;
                uint4 ua = {f2tf32(pa[i].x), f2tf32(pa[i].y), f2tf32(pa[i].z), f2tf32(pa[i].w)};
                uint4 ub = {f2tf32(pb[i].x), f2tf32(pb[i].y), f2tf32(pb[i].z), f2tf32(pb[i].w)};
                *(uint4*)&sm.ld.A[buf ^ 1][row][kq * 4] = ua;
                *(uint4*)&sm.ld.B[buf ^ 1][row][kq * 4] = ub;
            }
        }
        __syncthreads();
    }

#pragma unroll
    for (int mt = 0; mt < 2; mt++)
#pragma unroll
        for (int nt = 0; nt < 4; nt++) {
            int r  = wm + mt * 16 + gid;
            int cb = wn + nt * 8 + 2 * tig;
            sm.Cs[r][cb]     = c[mt][nt][0];
            sm.Cs[r][cb + 1] = c[mt][nt][1];
            sm.Cs[r + 8][cb]     = c[mt][nt][2];
            sm.Cs[r + 8][cb + 1] = c[mt][nt][3];
        }
    __syncthreads();

#pragma unroll
    for (int i = 0; i < 8; i++) {
        int s = tid + i * 128;
        int row = s >> 4, cq = s & 15;
        int colb = n0 + cq * 4;
        if (colb < N) {
            float4 v = *(float4*)&sm.Cs[row][cq * 4];
            float4 b1 = *(const float4*)&bias1[colb];
            v.x += b1.x; v.y += b1.y; v.z += b1.z; v.w += b1.w;
            if (bias2) {
                float4 b2 = *(const float4*)&bias2[colb];
                v.x += b2.x; v.y += b2.y; v.z += b2.z; v.w += b2.w;
            }
            int m = m0 + row;
            int orow = remap ? ((m & 63) * 256 + (m >> 6)) : m;
            *(float4*)&C[(size_t)orow * N + colb] = v;
        }
    }
}

// ---------------- Sigma = (L*fv) @ L^T + diag(idio) ----------------
__global__ __launch_bounds__(256) void sigma_kernel(float* __restrict__ out)
{
    __shared__ float fvs[32];
    __shared__ float Ln[32][64];
    __shared__ float Lm[32][64];

    const int b  = blockIdx.z;
    const int n0 = blockIdx.y * 64;
    const int m0 = blockIdx.x * 64;
    const int tid = threadIdx.x;
    const int tx = tid & 15;
    const int ty = tid >> 4;
    const float* rb = g_raw + (size_t)b * RAWN;

    if (tid < 32) fvs[tid] = expf(rb[NA * NF + tid]);
    __syncthreads();

#pragma unroll
    for (int i = 0; i < 8; i++) {
        int idx = tid + i * 256;
        int nl = idx >> 5, f = idx & 31;
        int n = n0 + nl;
        float v = (n < NA) ? rb[n * NF + f] : 0.f;
        Ln[f][nl] = v * fvs[f];
        int m = m0 + nl;
        float w = (m < NA) ? rb[m * NF + f] : 0.f;
        Lm[f][nl] = w;
    }
    __syncthreads();

    float acc[4][4];
#pragma unroll
    for (int r = 0; r < 4; r++)
#pragma unroll
        for (int cc = 0; cc < 4; cc++) acc[r][cc] = 0.f;

#pragma unroll
    for (int f = 0; f < 32; f++) {
        float4 a = *reinterpret_cast<const float4*>(&Ln[f][ty * 4]);
        float4 bb = *reinterpret_cast<const float4*>(&Lm[f][tx * 4]);
        float av[4] = {a.x, a.y, a.z, a.w};
        float bv[4] = {bb.x, bb.y, bb.z, bb.w};
#pragma unroll
        for (int r = 0; r < 4; r++)
#pragma unroll
            for (int cc = 0; cc < 4; cc++)
                acc[r][cc] = fmaf(av[r], bv[cc], acc[r][cc]);
    }

    const int mBase = m0 + tx * 4;
    if (mBase < NA) {
#pragma unroll
        for (int r = 0; r < 4; r++) {
            int n = n0 + ty * 4 + r;
            if (n >= NA) continue;
            float o[4] = {acc[r][0], acc[r][1], acc[r][2], acc[r][3]};
            int d = n - mBase;
            if (d >= 0 && d < 4) o[d] += expf(rb[NA * NF + NF + n]);
            float4 ov = {o[0], o[1], o[2], o[3]};
            *reinterpret_cast<float4*>(&out[(size_t)b * NA * NA + (size_t)n * NA + mBase]) = ov;
        }
    }
}

// ---------------- launch ----------------
extern "C" void kernel_launch(void* const* d_in, const int* in_sizes, int n_in,
                              void* d_out, int out_size)
{
    const float* x     = (const float*)d_in[0];
    const float* w_ih0 = (const float*)d_in[1];
    const float* w_hh0 = (const float*)d_in[2];
    const float* b_ih0 = (const float*)d_in[3];
    const float* b_hh0 = (const float*)d_in[4];
    const float* w_ih1 = (const float*)d_in[5];
    const float* w_hh1 = (const float*)d_in[6];
    const float* b_ih1 = (const float*)d_in[7];
    const float* b_hh1 = (const float*)d_in[8];
    const float* fc_w  = (const float*)d_in[9];
    const float* fc_b  = (const float*)d_in[10];
    float* out = (float*)d_out;

    static bool attr_done = false;
    if (!attr_done) {
        cudaFuncSetAttribute(lstm_persist,
            cudaFuncAttributeMaxDynamicSharedMemorySize, SM_WORDS * 4);
        attr_done = true;
    }

    // -------- layer 0 --------
    gemm_tc<<<dim3(G4 / 64, (B_SZ * T_SZ) / 64), 128>>>(
        x, /*asel=*/0, w_ih0, b_ih0, b_hh0, /*csel=*/0,
        G4, IN_SZ, /*remap=*/1);
    lstm_persist<<<GRIDN, 256, SM_WORDS * 4>>>(w_hh0, /*layer=*/0);

    // -------- layer 1 --------
    gemm_tc<<<dim3(G4 / 64, (B_SZ * T_SZ) / 64), 128>>>(
        nullptr, /*asel=*/1, w_ih1, b_ih1, b_hh1, /*csel=*/0,
        G4, HID, /*remap=*/0);
    lstm_persist<<<GRIDN, 256, SM_WORDS * 4>>>(w_hh1, /*layer=*/1);
    // final h (t=63, odd) lives in g_hA

    // -------- FC: raw = h_last @ fc_w^T + fc_b --------
    gemm_tc<<<dim3((RAWN + 63) / 64, B_SZ / 64), 128>>>(
        nullptr, /*asel=*/2, fc_w, fc_b, nullptr, /*csel=*/1,
        RAWN, HID, /*remap=*/0);

    // -------- Sigma --------
    sigma_kernel<<<dim3(8, 8, B_SZ), 256>>>(out);
}

// round 6
// speedup vs baseline: 1.0100x; 1.0100x over previous
#include <cuda_runtime.h>
#include <math.h>
#include <stdint.h>

#define B_SZ   256
#define T_SZ   64
#define IN_SZ  500
#define HID    512
#define G4     2048
#define RAWN   16532
#define NA     500
#define NF     32
#define GRIDN  128

__device__ float g_xg[(size_t)T_SZ * B_SZ * G4];
__device__ float g_hseq[(size_t)T_SZ * B_SZ * HID];
__device__ float g_hA[B_SZ * HID];
__device__ float g_hB[B_SZ * HID];
__device__ float g_raw[(size_t)B_SZ * RAWN];
__device__ unsigned long long g_flags[GRIDN];

__device__ __forceinline__ float sigmf(float x) { return 1.f / (1.f + expf(-x)); }

__device__ __forceinline__ uint32_t f2tf32(float f) {
    uint32_t r;
    asm("cvt.rna.tf32.f32 %0, %1;" : "=r"(r) : "f"(f));
    return r;
}

__device__ __forceinline__ void mma_tf32(float* c, const uint32_t* a, const uint32_t* b) {
    asm volatile(
        "mma.sync.aligned.m16n8k8.row.col.f32.tf32.tf32.f32 "
        "{%0,%1,%2,%3}, {%4,%5,%6,%7}, {%8,%9}, {%0,%1,%2,%3};\n"
        : "+f"(c[0]), "+f"(c[1]), "+f"(c[2]), "+f"(c[3])
        : "r"(a[0]), "r"(a[1]), "r"(a[2]), "r"(a[3]), "r"(b[0]), "r"(b[1]));
}

__device__ __forceinline__ void ldsm_x4(uint32_t* r, uint32_t addr) {
    asm volatile("ldmatrix.sync.aligned.m8n8.x4.shared.b16 {%0,%1,%2,%3}, [%4];"
        : "=r"(r[0]), "=r"(r[1]), "=r"(r[2]), "=r"(r[3]) : "r"(addr));
}

__device__ __forceinline__ uint32_t smem_u32(const void* p) {
    uint32_t a;
    asm("{ .reg .u64 t; cvta.to.shared.u64 t, %1; cvt.u32.u64 %0, t; }" : "=r"(a) : "l"(p));
    return a;
}

// ================= persistent LSTM layer (ldmatrix + cp.async) =================
// 128 blocks (32 hid-chunks x 4 batch-chunks), 256 threads (8 warps).
// Tile: 64 batch x 64 gate-cols (16 hidden x 4 interleaved gates) x K=512.
// smem bytes: W [64][516]u32 @0 (132096), A 3 x [64][68]u32 @132096 (3*17408).
// Cs (gate staging, fp32 [64][68]) aliases A buffer 0.
#define W_STR 516
#define A_STR 68
#define OFF_A 132096
#define ABUF  17408
#define SM_BYTES (OFF_A + 3 * ABUF)    // 184320

__global__ __launch_bounds__(256, 1) void lstm_persist(
    const float* __restrict__ w_hh, int layer)
{
    extern __shared__ __align__(16) uint32_t smraw[];
    uint32_t* Wsm = smraw;
    float*    Cs  = (float*)(smraw + OFF_A / 4);
    const uint32_t smem = smem_u32(smraw);

    const int tid  = threadIdx.x;
    const int lane = tid & 31;
    const int warp = tid >> 5;
    const int wm   = (warp >> 1) * 16;
    const int wn   = (warp & 1) * 32;
    const int h0   = (blockIdx.x & 31) * 16;
    const int m0   = (blockIdx.x >> 5) * 64;

    // ---- load W slice once: row n (0..63) = w_hh row (n&3)*HID + h0 + (n>>2) ----
#pragma unroll
    for (int i = 0; i < 32; i++) {
        int s   = tid + (i << 8);          // 0..8191 float4 granules
        int row = s >> 7;
        int kq  = s & 127;
        int wr  = ((row & 3) << 9) + h0 + (row >> 2);
        float4 v = *(const float4*)&w_hh[(size_t)wr * HID + (kq << 2)];
        *(uint4*)&Wsm[row * W_STR + (kq << 2)] =
            make_uint4(f2tf32(v.x), f2tf32(v.y), f2tf32(v.z), f2tf32(v.w));
    }

    // ---- per-lane ldmatrix base addresses ----
    // A fragment (m16k8): lanes 0-15 rows wm+(lane&15) col 0; 16-31 same rows col+4
    const uint32_t aBase = smem + OFF_A
        + (uint32_t)(((wm + (lane & 15)) * A_STR + ((lane >> 4) & 1) * 4) << 2);
    // B fragment (2 n-tiles per x4): rows wn+(lane&7)+((lane&16)?8:0), col +4 if lane&8
    const uint32_t rB = wn + (lane & 7) + ((lane & 16) ? 8 : 0);
    const uint32_t bBase0 = smem + (uint32_t)((rB * W_STR + ((lane >> 3) & 1) * 4) << 2);
    const uint32_t bBase1 = bBase0 + 16 * W_STR * 4;

    const unsigned long long barBase =
        *(volatile unsigned long long*)&g_flags[blockIdx.x];

    float creg[4] = {0.f, 0.f, 0.f, 0.f};
    const int jj  = tid & 15;
    const int bl0 = tid >> 4;

    // staging constants: thread writes granule g of rows rb+16i
    const int sg = tid & 15;          // 16B granule within 64-float chunk
    const int srb = tid >> 4;         // base row

    __syncthreads();

    for (int t = 0; t < T_SZ; t++) {
        const float* h_in = (t & 1) ? g_hB : g_hA;
        float* h_out      = (t & 1) ? g_hA : g_hB;

        if (t > 0) {
            // ---- stage chunk c into buffer c%3 via cp.async.cg ----
#define STAGE(c)                                                               \
            {                                                                  \
                const float* src = h_in + (size_t)(m0 + srb) * HID             \
                                   + (c) * 64 + sg * 4;                        \
                uint32_t dst = smem + OFF_A + ((c) % 3) * ABUF                 \
                               + (uint32_t)((srb * A_STR + sg * 4) << 2);      \
                _Pragma("unroll")                                              \
                for (int i = 0; i < 4; i++) {                                  \
                    asm volatile("cp.async.cg.shared.global [%0], [%1], 16;"   \
                        :: "r"(dst + (uint32_t)(i * 16 * A_STR * 4)),          \
                           "l"(src + (size_t)i * 16 * HID));                   \
                }                                                              \
                asm volatile("cp.async.commit_group;" ::: "memory");           \
            }
            STAGE(0)
            STAGE(1)

            float c[4][4];
#pragma unroll
            for (int nt = 0; nt < 4; nt++)
#pragma unroll
                for (int q = 0; q < 4; q++) c[nt][q] = 0.f;

#pragma unroll 1
            for (int ck = 0; ck < 8; ck++) {
                if (ck < 7) asm volatile("cp.async.wait_group 1;" ::: "memory");
                else        asm volatile("cp.async.wait_group 0;" ::: "memory");
                __syncthreads();
                if (ck < 6) STAGE(ck + 2)

                const uint32_t ab = aBase + (uint32_t)((ck % 3) * ABUF);
                const uint32_t wb0 = bBase0 + (uint32_t)(ck * 256);
                const uint32_t wb1 = bBase1 + (uint32_t)(ck * 256);
#pragma unroll
                for (int k8 = 0; k8 < 8; k8++) {
                    uint32_t a[4], b0[4], b1[4];
                    ldsm_x4(a,  ab  + (uint32_t)(k8 * 32));
                    ldsm_x4(b0, wb0 + (uint32_t)(k8 * 32));
                    ldsm_x4(b1, wb1 + (uint32_t)(k8 * 32));
                    mma_tf32(c[0], a, b0);
                    mma_tf32(c[1], a, b0 + 2);
                    mma_tf32(c[2], a, b1);
                    mma_tf32(c[3], a, b1 + 2);
                }
            }
#undef STAGE
            __syncthreads();

            // ---- stage gates to Cs (aliases A buf0; all compute done) ----
            const int gid = lane >> 2, tig = lane & 3;
#pragma unroll
            for (int nt = 0; nt < 4; nt++) {
                int r  = wm + gid;
                int cb = wn + nt * 8 + 2 * tig;
                Cs[r * A_STR + cb]           = c[nt][0];
                Cs[r * A_STR + cb + 1]       = c[nt][1];
                Cs[(r + 8) * A_STR + cb]     = c[nt][2];
                Cs[(r + 8) * A_STR + cb + 1] = c[nt][3];
            }
            __syncthreads();
        }

        // ---- fused cell update (register-resident c) ----
        const float* xgt = g_xg + (size_t)t * B_SZ * G4;
        const int h = h0 + jj;
#pragma unroll
        for (int i = 0; i < 4; i++) {
            int bl = bl0 + i * 16;
            int b  = m0 + bl;
            const float* xgb = xgt + (size_t)b * G4;
            float gi, gf, gg, go;
            if (t > 0) {
                float4 gv = *(float4*)&Cs[bl * A_STR + jj * 4];
                gi = gv.x; gf = gv.y; gg = gv.z; go = gv.w;
            } else {
                gi = gf = gg = go = 0.f;
            }
            gi += xgb[h];
            gf += xgb[HID + h];
            gg += xgb[2 * HID + h];
            go += xgb[3 * HID + h];
            float cn = sigmf(gf) * creg[i] + sigmf(gi) * tanhf(gg);
            float hn = sigmf(go) * tanhf(cn);
            creg[i] = cn;
            float hr = __uint_as_float(f2tf32(hn));   // pre-round: GEMM sees same value
            h_out[b * HID + h] = hr;
            if (layer == 0) g_hseq[(size_t)t * B_SZ * HID + b * HID + h] = hr;
        }

        // ---- grid barrier (monotone distributed flags) ----
        if (t < T_SZ - 1) {
            __threadfence();
            __syncthreads();
            const unsigned long long tgt = barBase + (unsigned long long)(t + 1);
            if (tid == 0)
                *(volatile unsigned long long*)&g_flags[blockIdx.x] = tgt;
            if (tid < GRIDN) {
                while (*(volatile unsigned long long*)&g_flags[tid] < tgt)
                    __nanosleep(64);
            }
            __syncthreads();
        }
    }
}

// ---------------- tensor-core GEMM (mma.sync): C = A @ W^T + bias ----------------
union SmemT {
    struct { uint32_t A[2][64][36]; uint32_t B[2][64][36]; } ld;
    float Cs[64][72];
};

__global__ __launch_bounds__(128) void gemm_tc(
    const float* __restrict__ Aext, int asel,
    const float* __restrict__ W,
    const float* __restrict__ bias1, const float* __restrict__ bias2,
    int csel, int N, int K, int remap)
{
    __shared__ SmemT sm;
    const float* A = (asel == 0) ? Aext : (asel == 1 ? g_hseq : g_hA);
    float* C = csel ? g_raw : g_xg;

    const int tid  = threadIdx.x;
    const int lane = tid & 31;
    const int warp = tid >> 5;
    const int wm   = (warp >> 1) * 32;
    const int wn   = (warp & 1) * 32;
    const int gid  = lane >> 2;
    const int tig  = lane & 3;
    const int m0   = blockIdx.y * 64;
    const int n0   = blockIdx.x * 64;

    float c[2][4][4];
#pragma unroll
    for (int mt = 0; mt < 2; mt++)
#pragma unroll
        for (int nt = 0; nt < 4; nt++)
#pragma unroll
            for (int q = 0; q < 4; q++) c[mt][nt][q] = 0.f;

    const int ktiles = (K + 31) >> 5;

#pragma unroll
    for (int i = 0; i < 4; i++) {
        int s = tid + i * 128;
        int row = s >> 3, kq = s & 7;
        int kk = kq * 4;
        float4 va = make_float4(0, 0, 0, 0), vb = make_float4(0, 0, 0, 0);
        if (kk < K) {
            va = *(const float4*)&A[(size_t)(m0 + row) * K + kk];
            int wr = n0 + row;
            if (wr < N) vb = *(const float4*)&W[(size_t)wr * K + kk];
        }
        *(uint4*)&sm.ld.A[0][row][kq * 4] =
            make_uint4(f2tf32(va.x), f2tf32(va.y), f2tf32(va.z), f2tf32(va.w));
        *(uint4*)&sm.ld.B[0][row][kq * 4] =
            make_uint4(f2tf32(vb.x), f2tf32(vb.y), f2tf32(vb.z), f2tf32(vb.w));
    }
    __syncthreads();

    float4 pa[4], pb[4];
    for (int kt = 0; kt < ktiles; kt++) {
        const int buf = kt & 1;
        const bool pf = (kt + 1 < ktiles);
        const int k0n = (kt + 1) << 5;
        if (pf) {
#pragma unroll
            for (int i = 0; i < 4; i++) {
                int s = tid + i * 128;
                int row = s >> 3, kq = s & 7;
                int kk = k0n + kq * 4;
                pa[i] = make_float4(0, 0, 0, 0);
                pb[i] = make_float4(0, 0, 0, 0);
                if (kk < K) {
                    pa[i] = *(const float4*)&A[(size_t)(m0 + row) * K + kk];
                    int wr = n0 + row;
                    if (wr < N) pb[i] = *(const float4*)&W[(size_t)wr * K + kk];
                }
            }
        }
#pragma unroll
        for (int kk8 = 0; kk8 < 4; kk8++) {
            uint32_t af[2][4];
#pragma unroll
            for (int mt = 0; mt < 2; mt++) {
                int r = wm + mt * 16 + gid;
                af[mt][0] = sm.ld.A[buf][r][kk8 * 8 + tig];
                af[mt][1] = sm.ld.A[buf][r + 8][kk8 * 8 + tig];
                af[mt][2] = sm.ld.A[buf][r][kk8 * 8 + tig + 4];
                af[mt][3] = sm.ld.A[buf][r + 8][kk8 * 8 + tig + 4];
            }
#pragma unroll
            for (int nt = 0; nt < 4; nt++) {
                uint32_t bf[2];
                int cn = wn + nt * 8 + gid;
                bf[0] = sm.ld.B[buf][cn][kk8 * 8 + tig];
                bf[1] = sm.ld.B[buf][cn][kk8 * 8 + tig + 4];
                mma_tf32(c[0][nt], af[0], bf);
                mma_tf32(c[1][nt], af[1], bf);
            }
        }
        if (pf) {
#pragma unroll
            for (int i = 0; i < 4; i++) {
                int s = tid + i * 128;
                int row = s >> 3, kq = s & 7;
                *(uint4*)&sm.ld.A[buf ^ 1][row][kq * 4] =
                    make_uint4(f2tf32(pa[i].x), f2tf32(pa[i].y), f2tf32(pa[i].z), f2tf32(pa[i].w));
                *(uint4*)&sm.ld.B[buf ^ 1][row][kq * 4] =
                    make_uint4(f2tf32(pb[i].x), f2tf32(pb[i].y), f2tf32(pb[i].z), f2tf32(pb[i].w));
            }
        }
        __syncthreads();
    }

#pragma unroll
    for (int mt = 0; mt < 2; mt++)
#pragma unroll
        for (int nt = 0; nt < 4; nt++) {
            int r  = wm + mt * 16 + gid;
            int cb = wn + nt * 8 + 2 * tig;
            sm.Cs[r][cb]         = c[mt][nt][0];
            sm.Cs[r][cb + 1]     = c[mt][nt][1];
            sm.Cs[r + 8][cb]     = c[mt][nt][2];
            sm.Cs[r + 8][cb + 1] = c[mt][nt][3];
        }
    __syncthreads();

#pragma unroll
    for (int i = 0; i < 8; i++) {
        int s = tid + i * 128;
        int row = s >> 4, cq = s & 15;
        int colb = n0 + cq * 4;
        if (colb < N) {
            float4 v = *(float4*)&sm.Cs[row][cq * 4];
            float4 b1 = *(const float4*)&bias1[colb];
            v.x += b1.x; v.y += b1.y; v.z += b1.z; v.w += b1.w;
            if (bias2) {
                float4 b2 = *(const float4*)&bias2[colb];
                v.x += b2.x; v.y += b2.y; v.z += b2.z; v.w += b2.w;
            }
            int m = m0 + row;
            int orow = remap ? ((m & 63) * 256 + (m >> 6)) : m;
            *(float4*)&C[(size_t)orow * N + colb] = v;
        }
    }
}

// ---------------- Sigma = (L*fv) @ L^T + diag(idio) ----------------
__global__ __launch_bounds__(256) void sigma_kernel(float* __restrict__ out)
{
    __shared__ float fvs[32];
    __shared__ float Ln[32][64];
    __shared__ float Lm[32][64];

    const int b  = blockIdx.z;
    const int n0 = blockIdx.y * 64;
    const int m0 = blockIdx.x * 64;
    const int tid = threadIdx.x;
    const int tx = tid & 15;
    const int ty = tid >> 4;
    const float* rb = g_raw + (size_t)b * RAWN;

    if (tid < 32) fvs[tid] = expf(rb[NA * NF + tid]);
    __syncthreads();

#pragma unroll
    for (int i = 0; i < 8; i++) {
        int idx = tid + i * 256;
        int nl = idx >> 5, f = idx & 31;
        int n = n0 + nl;
        float v = (n < NA) ? rb[n * NF + f] : 0.f;
        Ln[f][nl] = v * fvs[f];
        int m = m0 + nl;
        float w = (m < NA) ? rb[m * NF + f] : 0.f;
        Lm[f][nl] = w;
    }
    __syncthreads();

    float acc[4][4];
#pragma unroll
    for (int r = 0; r < 4; r++)
#pragma unroll
        for (int cc = 0; cc < 4; cc++) acc[r][cc] = 0.f;

#pragma unroll
    for (int f = 0; f < 32; f++) {
        float4 a  = *reinterpret_cast<const float4*>(&Ln[f][ty * 4]);
        float4 bb = *reinterpret_cast<const float4*>(&Lm[f][tx * 4]);
        float av[4] = {a.x, a.y, a.z, a.w};
        float bv[4] = {bb.x, bb.y, bb.z, bb.w};
#pragma unroll
        for (int r = 0; r < 4; r++)
#pragma unroll
            for (int cc = 0; cc < 4; cc++)
                acc[r][cc] = fmaf(av[r], bv[cc], acc[r][cc]);
    }

    const int mBase = m0 + tx * 4;
    if (mBase < NA) {
#pragma unroll
        for (int r = 0; r < 4; r++) {
            int n = n0 + ty * 4 + r;
            if (n >= NA) continue;
            float o[4] = {acc[r][0], acc[r][1], acc[r][2], acc[r][3]};
            int d = n - mBase;
            if (d >= 0 && d < 4) o[d] += expf(rb[NA * NF + NF + n]);
            float4 ov = {o[0], o[1], o[2], o[3]};
            *reinterpret_cast<float4*>(&out[(size_t)b * NA * NA + (size_t)n * NA + mBase]) = ov;
        }
    }
}

// ---------------- launch ----------------
extern "C" void kernel_launch(void* const* d_in, const int* in_sizes, int n_in,
                              void* d_out, int out_size)
{
    const float* x     = (const float*)d_in[0];
    const float* w_ih0 = (const float*)d_in[1];
    const float* w_hh0 = (const float*)d_in[2];
    const float* b_ih0 = (const float*)d_in[3];
    const float* b_hh0 = (const float*)d_in[4];
    const float* w_ih1 = (const float*)d_in[5];
    const float* w_hh1 = (const float*)d_in[6];
    const float* b_ih1 = (const float*)d_in[7];
    const float* b_hh1 = (const float*)d_in[8];
    const float* fc_w  = (const float*)d_in[9];
    const float* fc_b  = (const float*)d_in[10];
    float* out = (float*)d_out;

    static bool attr_done = false;
    if (!attr_done) {
        cudaFuncSetAttribute(lstm_persist,
            cudaFuncAttributeMaxDynamicSharedMemorySize, SM_BYTES);
        attr_done = true;
    }

    // layer 0
    gemm_tc<<<dim3(G4 / 64, (B_SZ * T_SZ) / 64), 128>>>(
        x, 0, w_ih0, b_ih0, b_hh0, 0, G4, IN_SZ, 1);
    lstm_persist<<<GRIDN, 256, SM_BYTES>>>(w_hh0, 0);

    // layer 1
    gemm_tc<<<dim3(G4 / 64, (B_SZ * T_SZ) / 64), 128>>>(
        nullptr, 1, w_ih1, b_ih1, b_hh1, 0, G4, HID, 0);
    lstm_persist<<<GRIDN, 256, SM_BYTES>>>(w_hh1, 1);
    // final h (t=63, odd) in g_hA

    // FC
    gemm_tc<<<dim3((RAWN + 63) / 64, B_SZ / 64), 128>>>(
        nullptr, 2, fc_w, fc_b, nullptr, 1, RAWN, HID, 0);

    // Sigma
    sigma_kernel<<<dim3(8, 8, B_SZ), 256>>>(out);
}

// round 7
// speedup vs baseline: 1.2091x; 1.1972x over previous
#include <cuda_runtime.h>
#include <math.h>
#include <stdint.h>

#define B_SZ   256
#define T_SZ   64
#define IN_SZ  500
#define HID    512
#define G4     2048
#define RAWN   16532
#define NA     500
#define NF     32
#define GRIDN  128

__device__ float g_xg[(size_t)T_SZ * B_SZ * G4];
__device__ float g_hseq[(size_t)T_SZ * B_SZ * HID];
__device__ float g_hA[B_SZ * HID];
__device__ float g_hB[B_SZ * HID];
__device__ float g_raw[(size_t)B_SZ * RAWN];
__device__ unsigned long long g_flags[GRIDN];

__device__ __forceinline__ float sigmf(float x) { return 1.f / (1.f + expf(-x)); }

__device__ __forceinline__ uint32_t f2tf32(float f) {
    uint32_t r;
    asm("cvt.rna.tf32.f32 %0, %1;" : "=r"(r) : "f"(f));
    return r;
}

__device__ __forceinline__ void mma_tf32(float* c, const uint32_t* a, const uint32_t* b) {
    asm volatile(
        "mma.sync.aligned.m16n8k8.row.col.f32.tf32.tf32.f32 "
        "{%0,%1,%2,%3}, {%4,%5,%6,%7}, {%8,%9}, {%0,%1,%2,%3};\n"
        : "+f"(c[0]), "+f"(c[1]), "+f"(c[2]), "+f"(c[3])
        : "r"(a[0]), "r"(a[1]), "r"(a[2]), "r"(a[3]), "r"(b[0]), "r"(b[1]));
}

__device__ __forceinline__ void ldsm_x4(uint32_t* r, uint32_t addr) {
    asm volatile("ldmatrix.sync.aligned.m8n8.x4.shared.b16 {%0,%1,%2,%3}, [%4];"
        : "=r"(r[0]), "=r"(r[1]), "=r"(r[2]), "=r"(r[3]) : "r"(addr));
}

__device__ __forceinline__ uint32_t smem_u32(const void* p) {
    uint32_t a;
    asm("{ .reg .u64 t; cvta.to.shared.u64 t, %1; cvt.u32.u64 %0, t; }" : "=r"(a) : "l"(p));
    return a;
}

// ================= persistent LSTM layer (pair-private pipelines) =================
// 128 blocks (32 hid-chunks x 4 batch-chunks), 256 threads (8 warps = 4 pairs).
// Tile: 64 batch x 64 gate-cols (16 hid x 4 interleaved gates) x K=512.
// Pair p (= warp>>1) owns batch rows wm=p*16..+15; its 2 warps (wn=0/32) split
// the 64 gate cols. Pair-private A ring (4 bufs) + bar.sync(1+p, 64) only.
//
// smem bytes:
//   W   [64][516]u32                    @ 0        132096
//   A   4 pairs x 4 bufs x [16][68]u32  @ 132096    69632
//   xg  8 warps x 2048B                 @ 201728    16384    total 218112
// Cs (gate transpose, warp-private 2304B) aliases pair bufs 0-1 (safe post-iter7).
#define W_STR   516
#define A_STR   68
#define OFF_AP  132096
#define PAIR_ST 17408
#define BUF_ST  4352
#define OFF_XG  201728
#define SM_BYTES 218112

__global__ __launch_bounds__(256, 1) void lstm_persist(
    const float* __restrict__ w_hh, int layer)
{
    extern __shared__ __align__(16) uint32_t smraw[];
    uint32_t* Wsm = smraw;
    float*    smf = (float*)smraw;
    const uint32_t smem = smem_u32(smraw);

    const int tid  = threadIdx.x;
    const int lane = tid & 31;
    const int warp = tid >> 5;
    const int pair = warp >> 1;
    const int wh   = warp & 1;          // which gate-col half / staging row half
    const int wm   = pair * 16;
    const int wn   = wh * 32;
    const int h0   = (blockIdx.x & 31) * 16;
    const int m0   = (blockIdx.x >> 5) * 64;

    // ---- load W slice once: row n (0..63) = w_hh row (n&3)*HID + h0 + (n>>2) ----
#pragma unroll
    for (int i = 0; i < 32; i++) {
        int s   = tid + (i << 8);
        int row = s >> 7;
        int kq  = s & 127;
        int wr  = ((row & 3) << 9) + h0 + (row >> 2);
        float4 v = *(const float4*)&w_hh[(size_t)wr * HID + (kq << 2)];
        *(uint4*)&Wsm[row * W_STR + (kq << 2)] =
            make_uint4(f2tf32(v.x), f2tf32(v.y), f2tf32(v.z), f2tf32(v.w));
    }

    // ldmatrix bases
    const uint32_t pairBase = smem + OFF_AP + (uint32_t)pair * PAIR_ST;
    const uint32_t aFrag = pairBase
        + (uint32_t)(((lane & 15) * A_STR + (lane >> 4) * 4) << 2);
    const uint32_t rB = wn + (lane & 7) + ((lane & 16) ? 8 : 0);
    const uint32_t bBase0 = smem + (uint32_t)((rB * W_STR + ((lane >> 3) & 1) * 4) << 2);
    const uint32_t bBase1 = bBase0 + 16 * W_STR * 4;

    // staging constants (h): this warp stages rows wm + wh*8 .. +7
    const int sRowBase = wh * 8;
    // xg smem (warp-private)
    const uint32_t xgBase = smem + OFF_XG + (uint32_t)warp * 2048;
    const int xgW = (int)(OFF_XG / 4) + warp * 512;
    // Cs (warp-private, aliases pair bufs 0-1)
    const int csW = (int)(OFF_AP / 4) + pair * (PAIR_ST / 4) + wh * 576;  // stride 36 words

    const unsigned long long barBase =
        *(volatile unsigned long long*)&g_flags[blockIdx.x];

    float creg[4] = {0.f, 0.f, 0.f, 0.f};
    const int barId = 1 + pair;

    __syncthreads();   // W visible to all

    // ---- prefetch xg for t=0 ----
    {
#pragma unroll
        for (int i = 0; i < 4; i++) {
            int idx = lane + 32 * i;
            int q = idx >> 5, r = (idx >> 1) & 15, gg = idx & 1;
            const float* src = g_xg + ((size_t)0 * B_SZ + m0 + wm + r) * G4
                             + q * HID + h0 + wh * 8 + gg * 4;
            asm volatile("cp.async.cg.shared.global [%0], [%1], 16;"
                :: "r"(xgBase + (uint32_t)(q * 512 + r * 32 + gg * 16)), "l"(src));
        }
        asm volatile("cp.async.commit_group;" ::: "memory");
    }

#define STAGE_H(c)                                                              \
    {                                                                           \
        uint32_t dbuf = pairBase + (uint32_t)(((c) & 3) * BUF_ST);              \
        _Pragma("unroll")                                                       \
        for (int i = 0; i < 4; i++) {                                           \
            int idx = lane + 32 * i;                                            \
            int rl = sRowBase + (idx >> 4);                                     \
            int gr = idx & 15;                                                  \
            const float* src = h_in + (size_t)(m0 + wm + rl) * HID              \
                             + (c) * 64 + gr * 4;                              \
            asm volatile("cp.async.cg.shared.global [%0], [%1], 16;"            \
                :: "r"(dbuf + (uint32_t)(rl * 272 + gr * 16)), "l"(src));       \
        }                                                                       \
        asm volatile("cp.async.commit_group;" ::: "memory");                    \
    }

#define MMA_CHUNK(ck)                                                           \
    {                                                                           \
        const uint32_t ab  = aFrag  + (uint32_t)(((ck) & 3) * BUF_ST);          \
        const uint32_t wb0 = bBase0 + (uint32_t)((ck) * 256);                   \
        const uint32_t wb1 = bBase1 + (uint32_t)((ck) * 256);                   \
        _Pragma("unroll")                                                       \
        for (int k8 = 0; k8 < 8; k8++) {                                        \
            uint32_t a[4], b0[4], b1[4];                                        \
            ldsm_x4(a,  ab  + (uint32_t)(k8 * 32));                             \
            ldsm_x4(b0, wb0 + (uint32_t)(k8 * 32));                             \
            ldsm_x4(b1, wb1 + (uint32_t)(k8 * 32));                             \
            mma_tf32(c[0], a, b0);                                              \
            mma_tf32(c[1], a, b0 + 2);                                          \
            mma_tf32(c[2], a, b1);                                              \
            mma_tf32(c[3], a, b1 + 2);                                          \
        }                                                                       \
    }

    for (int t = 0; t < T_SZ; t++) {
        const float* h_in = (t & 1) ? g_hB : g_hA;
        float* h_out      = (t & 1) ? g_hA : g_hB;

        float c[4][4];
#pragma unroll
        for (int nt = 0; nt < 4; nt++)
#pragma unroll
            for (int q = 0; q < 4; q++) c[nt][q] = 0.f;

        if (t > 0) {
            STAGE_H(0) STAGE_H(1) STAGE_H(2)
            // iter ck: wait(W) -> pair bar -> stage c(ck+3) -> MMA(ck)
#define ITER(ck, WN)                                                            \
            asm volatile("cp.async.wait_group " #WN ";" ::: "memory");          \
            asm volatile("bar.sync %0, 64;" :: "r"(barId) : "memory");          \
            if ((ck) <= 4) STAGE_H((ck) + 3)                                    \
            MMA_CHUNK(ck)
            ITER(0, 2) ITER(1, 2) ITER(2, 2) ITER(3, 2)
            ITER(4, 2) ITER(5, 2) ITER(6, 1) ITER(7, 0)
#undef ITER
            // ---- transpose gates via warp-private smem ----
            {
                const int gid = lane >> 2, tig = lane & 3;
#pragma unroll
                for (int nt = 0; nt < 4; nt++) {
                    int cb = nt * 8 + 2 * tig;
                    smf[csW + gid * 36 + cb]           = c[nt][0];
                    smf[csW + gid * 36 + cb + 1]       = c[nt][1];
                    smf[csW + (gid + 8) * 36 + cb]     = c[nt][2];
                    smf[csW + (gid + 8) * 36 + cb + 1] = c[nt][3];
                }
            }
        } else {
            asm volatile("cp.async.wait_group 0;" ::: "memory");  // xg(t=0)
        }
        __syncwarp();

        // ---- epilogue: lane owns 4 cells: row wm+(lane>>1), hid (wh*8)+(lane&1)*4.. ----
        {
            const int rl = lane >> 1;
            const int hq = lane & 1;
            float4 gv[4];   // per-cell gates (i,f,g,o) from Cs
            if (t > 0) {
#pragma unroll
                for (int k = 0; k < 4; k++)
                    gv[k] = *(float4*)&smf[csW + rl * 36 + hq * 16 + 4 * k];
            } else {
#pragma unroll
                for (int k = 0; k < 4; k++) gv[k] = make_float4(0, 0, 0, 0);
            }
            float4 xq[4];   // per-gate xg for the 4 hid
#pragma unroll
            for (int q = 0; q < 4; q++)
                xq[q] = *(float4*)&smf[xgW + q * 128 + rl * 8 + hq * 4];

            float xiv[4] = {xq[0].x, xq[0].y, xq[0].z, xq[0].w};
            float xfv[4] = {xq[1].x, xq[1].y, xq[1].z, xq[1].w};
            float xgv[4] = {xq[2].x, xq[2].y, xq[2].z, xq[2].w};
            float xov[4] = {xq[3].x, xq[3].y, xq[3].z, xq[3].w};

            uint32_t hb[4];
#pragma unroll
            for (int k = 0; k < 4; k++) {
                float gi = gv[k].x + xiv[k];
                float gf = gv[k].y + xfv[k];
                float gg = gv[k].z + xgv[k];
                float go = gv[k].w + xov[k];
                float cn = sigmf(gf) * creg[k] + sigmf(gi) * tanhf(gg);
                float hn = sigmf(go) * tanhf(cn);
                creg[k] = cn;
                hb[k] = f2tf32(hn);
            }
            const int b = m0 + wm + rl;
            const int hh = h0 + wh * 8 + hq * 4;
            *(uint4*)&h_out[(size_t)b * HID + hh] = make_uint4(hb[0], hb[1], hb[2], hb[3]);
            if (layer == 0)
                *(uint4*)&g_hseq[((size_t)t * B_SZ + b) * HID + hh] =
                    make_uint4(hb[0], hb[1], hb[2], hb[3]);
        }

        // ---- prefetch xg for t+1 (lands during barrier) ----
        if (t + 1 < T_SZ) {
#pragma unroll
            for (int i = 0; i < 4; i++) {
                int idx = lane + 32 * i;
                int q = idx >> 5, r = (idx >> 1) & 15, gg = idx & 1;
                const float* src = g_xg + ((size_t)(t + 1) * B_SZ + m0 + wm + r) * G4
                                 + q * HID + h0 + wh * 8 + gg * 4;
                asm volatile("cp.async.cg.shared.global [%0], [%1], 16;"
                    :: "r"(xgBase + (uint32_t)(q * 512 + r * 32 + gg * 16)), "l"(src));
            }
            asm volatile("cp.async.commit_group;" ::: "memory");

            // ---- grid barrier (release/acquire, hot spin) ----
            __syncthreads();
            const unsigned long long tgt = barBase + (unsigned long long)(t + 1);
            if (tid == 0)
                asm volatile("st.release.gpu.global.u64 [%0], %1;"
                             :: "l"(&g_flags[blockIdx.x]), "l"(tgt) : "memory");
            if (tid < GRIDN) {
                unsigned long long v;
                do {
                    asm volatile("ld.acquire.gpu.global.u64 %0, [%1];"
                                 : "=l"(v) : "l"(&g_flags[tid]) : "memory");
                } while (v < tgt);
            }
            __syncthreads();
        }
    }
#undef STAGE_H
#undef MMA_CHUNK
}

// ---------------- tensor-core GEMM (mma.sync): C = A @ W^T + bias ----------------
union SmemT {
    struct { uint32_t A[2][64][36]; uint32_t B[2][64][36]; } ld;
    float Cs[64][72];
};

__global__ __launch_bounds__(128) void gemm_tc(
    const float* __restrict__ Aext, int asel,
    const float* __restrict__ W,
    const float* __restrict__ bias1, const float* __restrict__ bias2,
    int csel, int N, int K, int remap)
{
    __shared__ SmemT sm;
    const float* A = (asel == 0) ? Aext : (asel == 1 ? g_hseq : g_hA);
    float* C = csel ? g_raw : g_xg;

    const int tid  = threadIdx.x;
    const int lane = tid & 31;
    const int warp = tid >> 5;
    const int wm   = (warp >> 1) * 32;
    const int wn   = (warp & 1) * 32;
    const int gid  = lane >> 2;
    const int tig  = lane & 3;
    const int m0   = blockIdx.y * 64;
    const int n0   = blockIdx.x * 64;

    float c[2][4][4];
#pragma unroll
    for (int mt = 0; mt < 2; mt++)
#pragma unroll
        for (int nt = 0; nt < 4; nt++)
#pragma unroll
            for (int q = 0; q < 4; q++) c[mt][nt][q] = 0.f;

    const int ktiles = (K + 31) >> 5;

#pragma unroll
    for (int i = 0; i < 4; i++) {
        int s = tid + i * 128;
        int row = s >> 3, kq = s & 7;
        int kk = kq * 4;
        float4 va = make_float4(0, 0, 0, 0), vb = make_float4(0, 0, 0, 0);
        if (kk < K) {
            va = *(const float4*)&A[(size_t)(m0 + row) * K + kk];
            int wr = n0 + row;
            if (wr < N) vb = *(const float4*)&W[(size_t)wr * K + kk];
        }
        *(uint4*)&sm.ld.A[0][row][kq * 4] =
            make_uint4(f2tf32(va.x), f2tf32(va.y), f2tf32(va.z), f2tf32(va.w));
        *(uint4*)&sm.ld.B[0][row][kq * 4] =
            make_uint4(f2tf32(vb.x), f2tf32(vb.y), f2tf32(vb.z), f2tf32(vb.w));
    }
    __syncthreads();

    float4 pa[4], pb[4];
    for (int kt = 0; kt < ktiles; kt++) {
        const int buf = kt & 1;
        const bool pf = (kt + 1 < ktiles);
        const int k0n = (kt + 1) << 5;
        if (pf) {
#pragma unroll
            for (int i = 0; i < 4; i++) {
                int s = tid + i * 128;
                int row = s >> 3, kq = s & 7;
                int kk = k0n + kq * 4;
                pa[i] = make_float4(0, 0, 0, 0);
                pb[i] = make_float4(0, 0, 0, 0);
                if (kk < K) {
                    pa[i] = *(const float4*)&A[(size_t)(m0 + row) * K + kk];
                    int wr = n0 + row;
                    if (wr < N) pb[i] = *(const float4*)&W[(size_t)wr * K + kk];
                }
            }
        }
#pragma unroll
        for (int kk8 = 0; kk8 < 4; kk8++) {
            uint32_t af[2][4];
#pragma unroll
            for (int mt = 0; mt < 2; mt++) {
                int r = wm + mt * 16 + gid;
                af[mt][0] = sm.ld.A[buf][r][kk8 * 8 + tig];
                af[mt][1] = sm.ld.A[buf][r + 8][kk8 * 8 + tig];
                af[mt][2] = sm.ld.A[buf][r][kk8 * 8 + tig + 4];
                af[mt][3] = sm.ld.A[buf][r + 8][kk8 * 8 + tig + 4];
            }
#pragma unroll
            for (int nt = 0; nt < 4; nt++) {
                uint32_t bf[2];
                int cn = wn + nt * 8 + gid;
                bf[0] = sm.ld.B[buf][cn][kk8 * 8 + tig];
                bf[1] = sm.ld.B[buf][cn][kk8 * 8 + tig + 4];
                mma_tf32(c[0][nt], af[0], bf);
                mma_tf32(c[1][nt], af[1], bf);
            }
        }
        if (pf) {
#pragma unroll
            for (int i = 0; i < 4; i++) {
                int s = tid + i * 128;
                int row = s >> 3, kq = s & 7;
                *(uint4*)&sm.ld.A[buf ^ 1][row][kq * 4] =
                    make_uint4(f2tf32(pa[i].x), f2tf32(pa[i].y), f2tf32(pa[i].z), f2tf32(pa[i].w));
                *(uint4*)&sm.ld.B[buf ^ 1][row][kq * 4] =
                    make_uint4(f2tf32(pb[i].x), f2tf32(pb[i].y), f2tf32(pb[i].z), f2tf32(pb[i].w));
            }
        }
        __syncthreads();
    }

#pragma unroll
    for (int mt = 0; mt < 2; mt++)
#pragma unroll
        for (int nt = 0; nt < 4; nt++) {
            int r  = wm + mt * 16 + gid;
            int cb = wn + nt * 8 + 2 * tig;
            sm.Cs[r][cb]         = c[mt][nt][0];
            sm.Cs[r][cb + 1]     = c[mt][nt][1];
            sm.Cs[r + 8][cb]     = c[mt][nt][2];
            sm.Cs[r + 8][cb + 1] = c[mt][nt][3];
        }
    __syncthreads();

#pragma unroll
    for (int i = 0; i < 8; i++) {
        int s = tid + i * 128;
        int row = s >> 4, cq = s & 15;
        int colb = n0 + cq * 4;
        if (colb < N) {
            float4 v = *(float4*)&sm.Cs[row][cq * 4];
            float4 b1 = *(const float4*)&bias1[colb];
            v.x += b1.x; v.y += b1.y; v.z += b1.z; v.w += b1.w;
            if (bias2) {
                float4 b2 = *(const float4*)&bias2[colb];
                v.x += b2.x; v.y += b2.y; v.z += b2.z; v.w += b2.w;
            }
            int m = m0 + row;
            int orow = remap ? ((m & 63) * 256 + (m >> 6)) : m;
            *(float4*)&C[(size_t)orow * N + colb] = v;
        }
    }
}

// ---------------- Sigma = (L*fv) @ L^T + diag(idio) ----------------
__global__ __launch_bounds__(256) void sigma_kernel(float* __restrict__ out)
{
    __shared__ float fvs[32];
    __shared__ float Ln[32][64];
    __shared__ float Lm[32][64];

    const int b  = blockIdx.z;
    const int n0 = blockIdx.y * 64;
    const int m0 = blockIdx.x * 64;
    const int tid = threadIdx.x;
    const int tx = tid & 15;
    const int ty = tid >> 4;
    const float* rb = g_raw + (size_t)b * RAWN;

    if (tid < 32) fvs[tid] = expf(rb[NA * NF + tid]);
    __syncthreads();

#pragma unroll
    for (int i = 0; i < 8; i++) {
        int idx = tid + i * 256;
        int nl = idx >> 5, f = idx & 31;
        int n = n0 + nl;
        float v = (n < NA) ? rb[n * NF + f] : 0.f;
        Ln[f][nl] = v * fvs[f];
        int m = m0 + nl;
        float w = (m < NA) ? rb[m * NF + f] : 0.f;
        Lm[f][nl] = w;
    }
    __syncthreads();

    float acc[4][4];
#pragma unroll
    for (int r = 0; r < 4; r++)
#pragma unroll
        for (int cc = 0; cc < 4; cc++) acc[r][cc] = 0.f;

#pragma unroll
    for (int f = 0; f < 32; f++) {
        float4 a  = *reinterpret_cast<const float4*>(&Ln[f][ty * 4]);
        float4 bb = *reinterpret_cast<const float4*>(&Lm[f][tx * 4]);
        float av[4] = {a.x, a.y, a.z, a.w};
        float bv[4] = {bb.x, bb.y, bb.z, bb.w};
#pragma unroll
        for (int r = 0; r < 4; r++)
#pragma unroll
            for (int cc = 0; cc < 4; cc++)
                acc[r][cc] = fmaf(av[r], bv[cc], acc[r][cc]);
    }

    const int mBase = m0 + tx * 4;
    if (mBase < NA) {
#pragma unroll
        for (int r = 0; r < 4; r++) {
            int n = n0 + ty * 4 + r;
            if (n >= NA) continue;
            float o[4] = {acc[r][0], acc[r][1], acc[r][2], acc[r][3]};
            int d = n - mBase;
            if (d >= 0 && d < 4) o[d] += expf(rb[NA * NF + NF + n]);
            float4 ov = {o[0], o[1], o[2], o[3]};
            *reinterpret_cast<float4*>(&out[(size_t)b * NA * NA + (size_t)n * NA + mBase]) = ov;
        }
    }
}

// ---------------- launch ----------------
extern "C" void kernel_launch(void* const* d_in, const int* in_sizes, int n_in,
                              void* d_out, int out_size)
{
    const float* x     = (const float*)d_in[0];
    const float* w_ih0 = (const float*)d_in[1];
    const float* w_hh0 = (const float*)d_in[2];
    const float* b_ih0 = (const float*)d_in[3];
    const float* b_hh0 = (const float*)d_in[4];
    const float* w_ih1 = (const float*)d_in[5];
    const float* w_hh1 = (const float*)d_in[6];
    const float* b_ih1 = (const float*)d_in[7];
    const float* b_hh1 = (const float*)d_in[8];
    const float* fc_w  = (const float*)d_in[9];
    const float* fc_b  = (const float*)d_in[10];
    float* out = (float*)d_out;

    static bool attr_done = false;
    if (!attr_done) {
        cudaFuncSetAttribute(lstm_persist,
            cudaFuncAttributeMaxDynamicSharedMemorySize, SM_BYTES);
        attr_done = true;
    }

    // layer 0
    gemm_tc<<<dim3(G4 / 64, (B_SZ * T_SZ) / 64), 128>>>(
        x, 0, w_ih0, b_ih0, b_hh0, 0, G4, IN_SZ, 1);
    lstm_persist<<<GRIDN, 256, SM_BYTES>>>(w_hh0, 0);

    // layer 1
    gemm_tc<<<dim3(G4 / 64, (B_SZ * T_SZ) / 64), 128>>>(
        nullptr, 1, w_ih1, b_ih1, b_hh1, 0, G4, HID, 0);
    lstm_persist<<<GRIDN, 256, SM_BYTES>>>(w_hh1, 1);
    // final h (t=63, odd) in g_hA

    // FC
    gemm_tc<<<dim3((RAWN + 63) / 64, B_SZ / 64), 128>>>(
        nullptr, 2, fc_w, fc_b, nullptr, 1, RAWN, HID, 0);

    // Sigma
    sigma_kernel<<<dim3(8, 8, B_SZ), 256>>>(out);
}